// round 12
// baseline (speedup 1.0000x reference)
#include <cuda_runtime.h>
#include <cuda_fp16.h>
#include <cstdint>

// Problem constants
#define BATCH 32
#define SEQ   2048
#define E     1024
#define MROWS (BATCH * SEQ)  // 65536

// Device scratch (static: no allocation allowed)
__device__ __half g_enc_h[(size_t)MROWS * E];   // fp16 copy of encoder_outputs (128 MB)
__device__ __half g_w1t_h[(size_t)E * E];       // w1 transposed, fp16: w1t[e][d]
__device__ float  g_qq[BATCH * E];
__device__ float  g_scores[BATCH * SEQ];
__device__ float  g_attn[BATCH * SEQ];
__device__ float  g_part[8 * BATCH * E];

// ---------------------------------------------------------------------------
// scores geometry: CTA = 64 rows x full E. 4 N-passes of BN=256.
// K stage = 32 halves (64B rows). 4-stage cp.async pipeline, 128 flat steps.
// 2 CTAs/SM for latency hiding.
// ---------------------------------------------------------------------------
#define BM 64
#define BN 256
#define BK 32
#define NSTAGE 4
#define NSTEPS 128                    // 4 passes * 32 k-steps

#define A_BYTES (BM * 64)             // 4096
#define B_BYTES (BN * 64)             // 16384
#define STAGE_BYTES (A_BYTES + B_BYTES)  // 20480
#define SM_SCORE 0
#define SM_EP    512
#define SM_STAGE 2560
#define SMEM_TOTAL (SM_STAGE + NSTAGE * STAGE_BYTES)   // 84480

// ---------------------------------------------------------------------------
// helpers
// ---------------------------------------------------------------------------
__device__ __forceinline__ uint32_t smem_u32(const void* p) {
    uint32_t a;
    asm("{ .reg .u64 t; cvta.to.shared.u64 t, %1; cvt.u32.u64 %0, t; }" : "=r"(a) : "l"(p));
    return a;
}
__device__ __forceinline__ void cp_async16(uint32_t dst, const void* src) {
    asm volatile("cp.async.cg.shared.global [%0], [%1], 16;" :: "r"(dst), "l"(src));
}
__device__ __forceinline__ void cp_commit() {
    asm volatile("cp.async.commit_group;" ::: "memory");
}
template <int N>
__device__ __forceinline__ void cp_wait() {
    asm volatile("cp.async.wait_group %0;" :: "n"(N) : "memory");
}
__device__ __forceinline__ void ldsm_x4(uint32_t d[4], uint32_t addr) {
    asm volatile("ldmatrix.sync.aligned.m8n8.x4.shared.b16 {%0,%1,%2,%3}, [%4];"
                 : "=r"(d[0]), "=r"(d[1]), "=r"(d[2]), "=r"(d[3]) : "r"(addr));
}
__device__ __forceinline__ void mma_f16(float c[4], const uint32_t a[4],
                                        uint32_t b0, uint32_t b1) {
    asm volatile(
        "mma.sync.aligned.m16n8k16.row.col.f32.f16.f16.f32 "
        "{%0,%1,%2,%3}, {%4,%5,%6,%7}, {%8,%9}, {%0,%1,%2,%3};\n"
        : "+f"(c[0]), "+f"(c[1]), "+f"(c[2]), "+f"(c[3])
        : "r"(a[0]), "r"(a[1]), "r"(a[2]), "r"(a[3]), "r"(b0), "r"(b1));
}

// ---------------------------------------------------------------------------
// conversion kernels
// ---------------------------------------------------------------------------
__global__ void conv_enc_kernel(const float* __restrict__ enc) {
    size_t i = ((size_t)blockIdx.x * 256 + threadIdx.x) * 8;
    float4 f0 = *(const float4*)(enc + i);
    float4 f1 = *(const float4*)(enc + i + 4);
    __half2 h[4];
    h[0] = __floats2half2_rn(f0.x, f0.y);
    h[1] = __floats2half2_rn(f0.z, f0.w);
    h[2] = __floats2half2_rn(f1.x, f1.y);
    h[3] = __floats2half2_rn(f1.z, f1.w);
    *(uint4*)(g_enc_h + i) = *(uint4*)h;
}

__global__ void conv_w1t_kernel(const float* __restrict__ w1) {
    __shared__ float t[32][33];
    int bx = blockIdx.x * 32, by = blockIdx.y * 32;
    int x = threadIdx.x, y0 = threadIdx.y;
#pragma unroll
    for (int j = 0; j < 32; j += 8)
        t[y0 + j][x] = w1[(size_t)(by + y0 + j) * E + bx + x];
    __syncthreads();
#pragma unroll
    for (int j = 0; j < 32; j += 8)
        g_w1t_h[(size_t)(bx + y0 + j) * E + by + x] = __float2half_rn(t[x][y0 + j]);
}

// ---------------------------------------------------------------------------
// qq[b,e] = dec[b]@w2[:,e] + b1[e] + b2[e]   (fp32, small)
// ---------------------------------------------------------------------------
__global__ void qq_kernel(const float* __restrict__ dec, const float* __restrict__ w2,
                          const float* __restrict__ b1, const float* __restrict__ b2) {
    int b = blockIdx.x;
    int e = blockIdx.y * 128 + threadIdx.x;
    const float* drow = dec + (size_t)b * E;
    float acc = 0.f;
#pragma unroll 4
    for (int d = 0; d < E; d++) acc += __ldg(drow + d) * __ldg(w2 + (size_t)d * E + e);
    g_qq[b * E + e] = acc + __ldg(b1 + e) + __ldg(b2 + e);
}

// ---------------------------------------------------------------------------
// scores kernel: fp16 mma.sync m16n8k16 + ldmatrix, fused tanh/v-dot epilogue
// grid 1024 CTAs, 256 threads, 2 CTAs/SM
// ---------------------------------------------------------------------------
__global__ __launch_bounds__(256, 2)
void scores_kernel(const float* __restrict__ v) {
    extern __shared__ char smem[];
    const uint32_t sbase = smem_u32(smem);
    const int tid = threadIdx.x;
    const int warp = tid >> 5, lane = tid & 31;
    const int wm = warp & 1;          // 2 m-warps: 32 rows each
    const int wn = warp >> 1;         // 4 n-warps: 64 cols each
    const int grp = lane >> 2;        // 0..7
    const int tig = lane & 3;         // 0..3
    const int row0 = blockIdx.x * BM;
    const int b = row0 >> 11;

    // ldmatrix per-lane geometry (64B rows, 4x 16B chunks, swizzle c ^= (row>>1)&3)
    const int quad = lane >> 3, rin = lane & 7;
    const int qlow = quad & 1, qhi = quad >> 1;
    const int a_m = wm * 32 + qlow * 8 + rin;
    const int b_n = wn * 64 + qlow * 8 + rin;
    const int sw_a = (a_m >> 1) & 3;
    const int sw_b = (b_n >> 1) & 3;

    uint32_t offKa[2], offKb[2];
#pragma unroll
    for (int ks = 0; ks < 2; ks++) {
        offKa[ks] = (uint32_t)(((2 * ks + qhi) ^ sw_a) << 4);
        offKb[ks] = (uint32_t)(((2 * ks + qhi) ^ sw_b) << 4);
    }
    const uint32_t aoff = (uint32_t)a_m * 64;
    const uint32_t boff = A_BYTES + (uint32_t)b_n * 64;

    // cp.async per-thread geometry
    const __half* srcA;
    uint32_t dstA;
    {
        int m = tid >> 2, c = tid & 3;
        srcA = g_enc_h + (size_t)(row0 + m) * E + c * 8;
        dstA = (uint32_t)(m * 64 + ((c ^ ((m >> 1) & 3)) << 4));
    }
    const __half* srcB[4];
    uint32_t dstB[4];
#pragma unroll
    for (int j = 0; j < 4; j++) {
        int q = tid + j * 256;
        int n = q >> 2, c = q & 3;
        srcB[j] = g_w1t_h + (size_t)n * E + c * 8;      // pass 0 (n0 = 0)
        dstB[j] = (uint32_t)(A_BYTES + n * 64 + ((c ^ ((n >> 1) & 3)) << 4));
    }

    float* sScore = (float*)(smem + SM_SCORE);
    float* sEp = (float*)(smem + SM_EP);
    const float* qrow = g_qq + b * E;

    if (tid < BM) sScore[tid] = 0.f;

    // prologue: preload steps 0..2 (all pass 0)
#pragma unroll
    for (int s = 0; s < NSTAGE - 1; s++) {
        uint32_t sb = sbase + SM_STAGE + s * STAGE_BYTES;
        uint32_t koff = s * 32;       // halves
        cp_async16(sb + dstA, srcA + koff);
#pragma unroll
        for (int j = 0; j < 4; j++) cp_async16(sb + dstB[j], srcB[j] + koff);
        cp_commit();
    }

    float acc[2][8][4];
#pragma unroll
    for (int mf = 0; mf < 2; mf++)
#pragma unroll
        for (int nf = 0; nf < 8; nf++)
#pragma unroll
            for (int i = 0; i < 4; i++) acc[mf][nf][i] = 0.f;

#pragma unroll 1
    for (int i = 0; i < NSTEPS; i++) {
        cp_wait<NSTAGE - 2>();
        __syncthreads();

        // prefetch step i+3 into slot (i+3)&3 (consumed slot of step i-1)
        if (i < NSTEPS - (NSTAGE - 1)) {
            const int s = i + NSTAGE - 1;
            if ((s & 31) == 0) {      // next N pass: advance B bases
#pragma unroll
                for (int j = 0; j < 4; j++) srcB[j] += (size_t)BN * E;
            }
            const uint32_t sb = sbase + SM_STAGE + (s & 3) * STAGE_BYTES;
            const uint32_t koff = (s & 31) * 32;   // halves
            cp_async16(sb + dstA, srcA + koff);
#pragma unroll
            for (int j = 0; j < 4; j++) cp_async16(sb + dstB[j], srcB[j] + koff);
        }
        cp_commit();   // uniform group count (empty groups at tail)

        // compute stage i
        {
            const uint32_t stA = sbase + SM_STAGE + (i & 3) * STAGE_BYTES + aoff;
            const uint32_t stB = sbase + SM_STAGE + (i & 3) * STAGE_BYTES + boff;
#pragma unroll
            for (int ks = 0; ks < 2; ks++) {
                uint32_t af[2][4];
#pragma unroll
                for (int mf = 0; mf < 2; mf++)
                    ldsm_x4(af[mf], stA + mf * 1024 + offKa[ks]);
                uint32_t bf[4][4];
#pragma unroll
                for (int nfp = 0; nfp < 4; nfp++)
                    ldsm_x4(bf[nfp], stB + nfp * 1024 + offKb[ks]);
#pragma unroll
                for (int mf = 0; mf < 2; mf++)
#pragma unroll
                    for (int nfp = 0; nfp < 4; nfp++) {
                        mma_f16(acc[mf][2 * nfp],     af[mf], bf[nfp][0], bf[nfp][2]);
                        mma_f16(acc[mf][2 * nfp + 1], af[mf], bf[nfp][1], bf[nfp][3]);
                    }
            }
        }

        // epilogue at end of each N pass (every 32 steps)
        if ((i & 31) == 31) {
            const int n0 = (i >> 5) * BN;
#pragma unroll
            for (int mf = 0; mf < 2; mf++) {
                float sumA = 0.f, sumB = 0.f;
#pragma unroll
                for (int nf = 0; nf < 8; nf++) {
                    int c = n0 + wn * 64 + nf * 8 + tig * 2;
                    float q0 = __ldg(qrow + c), q1 = __ldg(qrow + c + 1);
                    float v0 = __ldg(v + c), v1 = __ldg(v + c + 1);
                    sumA += tanhf(acc[mf][nf][0] + q0) * v0 + tanhf(acc[mf][nf][1] + q1) * v1;
                    sumB += tanhf(acc[mf][nf][2] + q0) * v0 + tanhf(acc[mf][nf][3] + q1) * v1;
                }
                sumA += __shfl_xor_sync(0xffffffffu, sumA, 1);
                sumA += __shfl_xor_sync(0xffffffffu, sumA, 2);
                sumB += __shfl_xor_sync(0xffffffffu, sumB, 1);
                sumB += __shfl_xor_sync(0xffffffffu, sumB, 2);
                if (tig == 0) {
                    int r = wm * 32 + mf * 16 + grp;
                    sEp[wn * BM + r] = sumA;
                    sEp[wn * BM + r + 8] = sumB;
                }
            }
            __syncthreads();
            if (tid < BM)
                sScore[tid] += sEp[tid] + sEp[BM + tid] + sEp[2 * BM + tid] + sEp[3 * BM + tid];
#pragma unroll
            for (int mf = 0; mf < 2; mf++)
#pragma unroll
                for (int nf = 0; nf < 8; nf++)
#pragma unroll
                    for (int k2 = 0; k2 < 4; k2++) acc[mf][nf][k2] = 0.f;
        }
    }

    __syncthreads();
    if (tid < BM) g_scores[row0 + tid] = sScore[tid];
}

// ---------------------------------------------------------------------------
// Softmax over s per batch
// ---------------------------------------------------------------------------
__global__ void softmax_kernel() {
    const int b = blockIdx.x;
    const int tid = threadIdx.x;
    __shared__ float red[8];

    float vals[8];
    float mx = -1e30f;
#pragma unroll
    for (int i = 0; i < 8; i++) {
        vals[i] = g_scores[b * SEQ + i * 256 + tid];
        mx = fmaxf(mx, vals[i]);
    }
#pragma unroll
    for (int o = 16; o > 0; o >>= 1) mx = fmaxf(mx, __shfl_xor_sync(0xffffffffu, mx, o));
    if ((tid & 31) == 0) red[tid >> 5] = mx;
    __syncthreads();
    mx = red[0];
#pragma unroll
    for (int w = 1; w < 8; w++) mx = fmaxf(mx, red[w]);

    float sum = 0.f;
#pragma unroll
    for (int i = 0; i < 8; i++) {
        vals[i] = __expf(vals[i] - mx);
        sum += vals[i];
    }
#pragma unroll
    for (int o = 16; o > 0; o >>= 1) sum += __shfl_xor_sync(0xffffffffu, sum, o);
    __syncthreads();
    if ((tid & 31) == 0) red[tid >> 5] = sum;
    __syncthreads();
    sum = 0.f;
#pragma unroll
    for (int w = 0; w < 8; w++) sum += red[w];
    float inv = 1.f / sum;
#pragma unroll
    for (int i = 0; i < 8; i++) g_attn[b * SEQ + i * 256 + tid] = vals[i] * inv;
}

// ---------------------------------------------------------------------------
// Context (reads fp16 enc copy: half the DRAM traffic)
// ---------------------------------------------------------------------------
__global__ void ctx_partial_kernel() {
    const int b = blockIdx.x;
    const int e2 = blockIdx.y * 256 + threadIdx.x;   // half2 index, 0..511
    const int sc = blockIdx.z;
    __shared__ float sat[256];
    const int s0 = sc * 256;
    sat[threadIdx.x] = g_attn[b * SEQ + s0 + threadIdx.x];
    __syncthreads();
    const __half2* p = (const __half2*)(g_enc_h + ((size_t)b * SEQ + s0) * E) + e2;
    float ax = 0.f, ay = 0.f;
#pragma unroll 4
    for (int s = 0; s < 256; s++) {
        float2 f = __half22float2(p[(size_t)s * (E / 2)]);
        float a = sat[s];
        ax += a * f.x;
        ay += a * f.y;
    }
    float* dst = g_part + ((size_t)sc * BATCH + b) * E + 2 * e2;
    dst[0] = ax;
    dst[1] = ay;
}

__global__ void ctx_reduce_kernel(float* __restrict__ out) {
    int i = blockIdx.x * 256 + threadIdx.x;
    float a = 0.f;
#pragma unroll
    for (int sc = 0; sc < 8; sc++) a += g_part[(size_t)sc * BATCH * E + i];
    out[i] = a;
}

// ---------------------------------------------------------------------------
extern "C" void kernel_launch(void* const* d_in, const int* in_sizes, int n_in,
                              void* d_out, int out_size) {
    const float* enc = (const float*)d_in[0];
    const float* dec = (const float*)d_in[1];
    const float* w1  = (const float*)d_in[2];
    const float* b1  = (const float*)d_in[3];
    const float* w2  = (const float*)d_in[4];
    const float* b2  = (const float*)d_in[5];
    const float* v   = (const float*)d_in[6];
    // d_in[7] = bv: uniform shift under softmax -> no effect
    float* out = (float*)d_out;

    cudaFuncSetAttribute(scores_kernel, cudaFuncAttributeMaxDynamicSharedMemorySize, SMEM_TOTAL);

    conv_enc_kernel<<<MROWS * E / (256 * 8), 256>>>(enc);        // launch 0
    conv_w1t_kernel<<<dim3(32, 32), dim3(32, 8)>>>(w1);          // launch 1
    qq_kernel<<<dim3(BATCH, E / 128), 128>>>(dec, w2, b1, b2);   // launch 2
    scores_kernel<<<MROWS / BM, 256, SMEM_TOTAL>>>(v);           // launch 3 (ncu slot)
    softmax_kernel<<<BATCH, 256>>>();
    ctx_partial_kernel<<<dim3(BATCH, 2, SEQ / 256), 256>>>();
    ctx_reduce_kernel<<<BATCH * E / 256, 256>>>(out);
}